// round 17
// baseline (speedup 1.0000x reference)
#include <cuda_runtime.h>
#include <cuda_fp16.h>
#include <cstdint>

#define NN 100000
#define DF 64
#define NE 1600000
#define NB ((NN + 1023) / 1024)   // 98 scan blocks

static constexpr float DTC     = 0.2f;
static constexpr float HALF_DT = 0.1f;
static constexpr float DT6     = 0.2f / 6.0f;

// ---------------- scratch (static device globals) ----------------
__device__ int     g_deg1[NN];          // masked row degree (hop-1 CSR)
__device__ int     g_deg2[NN];          // full row degree   (hop-2 CSR)
__device__ int     g_deg_c[NN];         // full col degree
__device__ int     g_cur1[NN];
__device__ int     g_cur2[NN];
__device__ float   g_dinv_r[NN];        // row factor (applied to row sum)
__device__ float   g_premul[NN];        // mask * dinv_c (folded into u)
__device__ float   g_dd[NN];            // dinv_r * dinv_c (folded into t1)
__device__ int     g_rp1[NN + 1];
__device__ int     g_rp2[NN + 1];
__device__ int     g_part1[NB];
__device__ int     g_part2[NB];
__device__ int     g_ecol1[NE];         // masked CSR cols (~half used)
__device__ int     g_ecol2[NE];         // full CSR cols
__device__ __half2 g_uh [NN * DF / 2];  // stage input * mask*dinv_c, fp16
__device__ __half2 g_t1h[NN * DF / 2];  // hop-1 out * dinv_r*dinv_c, fp16
__device__ __half2 g_rh [NN * DF / 2];  // fp16 copy of current state r
__device__ uint4   g_acch[NN * DF / 8]; // k1 + 2k2 + 2k3, fp16 (4x half2)
// software grid barrier state (reset each call in zero_kernel)
__device__ volatile unsigned g_phase;
__device__ unsigned g_arrive;

// ---------------- preprocessing ----------------
__global__ void zero_kernel() {
    int i = blockIdx.x * blockDim.x + threadIdx.x;
    if (i < NN) { g_deg1[i] = 0; g_deg2[i] = 0; g_deg_c[i] = 0;
                  g_cur1[i] = 0; g_cur2[i] = 0; }
    if (i == 0) { g_phase = 0; g_arrive = 0; }
}

__global__ void hist_kernel(const int* __restrict__ row, const int* __restrict__ col,
                            const int* __restrict__ mask) {
    int e = blockIdx.x * blockDim.x + threadIdx.x;
    if (e < NE) {
        int r = row[e], c = col[e];
        atomicAdd(&g_deg2[r], 1);
        atomicAdd(&g_deg_c[c], 1);
        if (mask[c]) atomicAdd(&g_deg1[r], 1);
    }
}

__global__ void dinv_kernel(const int* __restrict__ mask) {
    int i = blockIdx.x * blockDim.x + threadIdx.x;
    if (i < NN) {
        int dr = g_deg2[i];
        int dc = g_deg_c[i];
        float ir = dr > 0 ? rsqrtf((float)dr) : 0.0f;
        float ic = dc > 0 ? rsqrtf((float)dc) : 0.0f;
        g_dinv_r[i] = ir;
        g_premul[i] = mask[i] ? ic : 0.0f;
        g_dd[i]     = ir * ic;
    }
}

// Fused two-level scans for BOTH CSRs (blocks [0,NB) -> CSR1, [NB,2NB) -> CSR2)
__global__ void scan_block_fused() {
    int bb = blockIdx.x;
    int isP2 = (bb >= NB);
    int b = isP2 ? bb - NB : bb;
    const int* __restrict__ deg = isP2 ? g_deg2  : g_deg1;
    int* __restrict__ rp        = isP2 ? g_rp2   : g_rp1;
    int* __restrict__ part      = isP2 ? g_part2 : g_part1;
    __shared__ int wsum[32];
    int t = threadIdx.x, lane = t & 31, wid = t >> 5;
    int i = b * 1024 + t;
    int v = (i < NN) ? deg[i] : 0;
    int incl = v;
    #pragma unroll
    for (int off = 1; off < 32; off <<= 1) {
        int x = __shfl_up_sync(0xffffffffu, incl, off);
        if (lane >= off) incl += x;
    }
    if (lane == 31) wsum[wid] = incl;
    __syncthreads();
    if (wid == 0) {
        int ws = wsum[lane];
        int wincl = ws;
        #pragma unroll
        for (int off = 1; off < 32; off <<= 1) {
            int x = __shfl_up_sync(0xffffffffu, wincl, off);
            if (lane >= off) wincl += x;
        }
        wsum[lane] = wincl - ws;
    }
    __syncthreads();
    int excl = incl - v + wsum[wid];
    if (i < NN) rp[i] = excl;
    if (t == 1023) part[b] = excl + v;
}

__global__ void scan_part_fused() {
    int t = threadIdx.x;
    if (t == 0) {
        int s = 0;
        for (int b = 0; b < NB; b++) { int v = g_part1[b]; g_part1[b] = s; s += v; }
        g_rp1[NN] = s;
    } else if (t == 32) {
        int s = 0;
        for (int b = 0; b < NB; b++) { int v = g_part2[b]; g_part2[b] = s; s += v; }
        g_rp2[NN] = s;
    }
}

__global__ void scan_add_fused() {
    int bb = blockIdx.x;
    int isP2 = (bb >= NB);
    int b = isP2 ? bb - NB : bb;
    int* __restrict__ rp         = isP2 ? g_rp2   : g_rp1;
    const int* __restrict__ part = isP2 ? g_part2 : g_part1;
    int i = b * 1024 + threadIdx.x;
    if (i < NN) rp[i] += part[b];
}

__global__ void scatter_kernel(const int* __restrict__ row, const int* __restrict__ col,
                               const int* __restrict__ mask) {
    int e = blockIdx.x * blockDim.x + threadIdx.x;
    if (e < NE) {
        int r = row[e], c = col[e];
        int p2 = g_rp2[r] + atomicAdd(&g_cur2[r], 1);
        g_ecol2[p2] = c;
        if (mask[c]) {
            int p1 = g_rp1[r] + atomicAdd(&g_cur1[r], 1);
            g_ecol1[p1] = c;
        }
    }
}

// ---------------- persistent mainloop ----------------
// software grid barrier: monotonic phase counter, ticket arrival.
// All blocks are guaranteed co-resident (grid = #SMs, 1 block/SM by
// __launch_bounds__(1024,1)).
__device__ __forceinline__ void grid_barrier(unsigned target) {
    __syncthreads();
    if (threadIdx.x == 0) {
        __threadfence();
        unsigned t = atomicAdd(&g_arrive, 1);
        if (t == gridDim.x - 1) {
            g_arrive = 0;           // all blocks have arrived
            __threadfence();
            g_phase = target;       // release (volatile store)
        } else {
            while (g_phase < target) __nanosleep(64);
            __threadfence();        // acquire
        }
    }
    __syncthreads();
}

struct Acc8 { float a0, a1, a2, a3, a4, a5, a6, a7; };

#define QACC(v) \
    { float2 f; \
      f = __half22float2(*(const __half2*)&(v).x); r.a0 += f.x; r.a1 += f.y; \
      f = __half22float2(*(const __half2*)&(v).y); r.a2 += f.x; r.a3 += f.y; \
      f = __half22float2(*(const __half2*)&(v).z); r.a4 += f.x; r.a5 += f.y; \
      f = __half22float2(*(const __half2*)&(v).w); r.a6 += f.x; r.a7 += f.y; }

__device__ __forceinline__ Acc8
row_gather_quarter(const __half2* __restrict__ x, const int* __restrict__ ec,
                   const int* __restrict__ rp, int row, int m) {
    int s = rp[row];
    int n_my = rp[row + 1] - s;
    int t = __shfl_xor_sync(0xffffffffu, n_my, 8);
    int nmax = max(n_my, t);
    t = __shfl_xor_sync(0xffffffffu, nmax, 16);
    nmax = max(nmax, t);
    const char* __restrict__ xb = (const char*)x;
    unsigned moff = m << 4;                       // 16 B per lane
    Acc8 r = {0.f, 0.f, 0.f, 0.f, 0.f, 0.f, 0.f, 0.f};

    for (int j0 = 0; j0 < nmax; j0 += 8) {
        int myidx = j0 + m;
        int c = (myidx < n_my) ? __ldg(&ec[s + myidx]) : 0;
        #pragma unroll
        for (int g = 0; g < 2; g++) {
            int b = j0 + g * 4;
            if (b >= nmax) break;                 // warp-uniform
            int c0 = __shfl_sync(0xffffffffu, c, g * 4 + 0, 8);
            int c1 = __shfl_sync(0xffffffffu, c, g * 4 + 1, 8);
            int c2 = __shfl_sync(0xffffffffu, c, g * 4 + 2, 8);
            int c3 = __shfl_sync(0xffffffffu, c, g * 4 + 3, 8);
            uint4 z = make_uint4(0u, 0u, 0u, 0u);
            uint4 v0 = (b + 0 < n_my) ? __ldg((const uint4*)(xb + (((size_t)c0) << 7) + moff)) : z;
            uint4 v1 = (b + 1 < n_my) ? __ldg((const uint4*)(xb + (((size_t)c1) << 7) + moff)) : z;
            uint4 v2 = (b + 2 < n_my) ? __ldg((const uint4*)(xb + (((size_t)c2) << 7) + moff)) : z;
            uint4 v3 = (b + 3 < n_my) ? __ldg((const uint4*)(xb + (((size_t)c3) << 7) + moff)) : z;
            QACC(v0) QACC(v1) QACC(v2) QACC(v3)
        }
    }
    return r;
}

__device__ __forceinline__ uint4 pack8h(float a, float b, float c, float d,
                                        float e, float f, float g, float h) {
    __half2 h0 = __floats2half2_rn(a, b);
    __half2 h1 = __floats2half2_rn(c, d);
    __half2 h2 = __floats2half2_rn(e, f);
    __half2 h3 = __floats2half2_rn(g, h);
    return make_uint4(*(const unsigned*)&h0, *(const unsigned*)&h1,
                      *(const unsigned*)&h2, *(const unsigned*)&h3);
}

__global__ void __launch_bounds__(1024, 1)
rk4_persistent(const float* __restrict__ r0, float* __restrict__ out) {
    int tid = blockIdx.x * blockDim.x + threadIdx.x;
    int nthreads = gridDim.x * blockDim.x;
    int gw = tid >> 5;
    int nwarps = nthreads >> 5;
    int lane = threadIdx.x & 31;
    int m = lane & 7;
    int qq = lane >> 3;

    // phase 0: out slice 0 = r0; uh = premul*r0; rh = fp16(r0)
    for (int i = tid; i < NN * DF / 4; i += nthreads) {
        float4 r = ((const float4*)r0)[i];
        ((float4*)out)[i] = r;
        int node = i >> 4;
        float p = g_premul[node];
        __half2 u0 = __floats2half2_rn(p * r.x, p * r.y);
        __half2 u1 = __floats2half2_rn(p * r.z, p * r.w);
        ((uint2*)g_uh)[i] = make_uint2(*(const unsigned*)&u0, *(const unsigned*)&u1);
        __half2 h0 = __floats2half2_rn(r.x, r.y);
        __half2 h1 = __floats2half2_rn(r.z, r.w);
        ((uint2*)g_rh)[i] = make_uint2(*(const unsigned*)&h0, *(const unsigned*)&h1);
    }
    unsigned bar = 0;
    grid_barrier(++bar);

    for (int step = 0; step < 5; step++) {
        const float* rin = out + (size_t)step * NN * DF;
        float* rnext     = out + (size_t)(step + 1) * NN * DF;

        for (int sub = 1; sub <= 4; sub++) {
            // ---- hop-1 ----
            for (int w = gw; w < NN / 4; w += nwarps) {
                int row = w * 4 + qq;
                Acc8 r = row_gather_quarter(g_uh, g_ecol1, g_rp1, row, m);
                float sc = g_dd[row];
                ((uint4*)g_t1h)[row * 8 + m] =
                    pack8h(sc * r.a0, sc * r.a1, sc * r.a2, sc * r.a3,
                           sc * r.a4, sc * r.a5, sc * r.a6, sc * r.a7);
            }
            grid_barrier(++bar);

            // ---- hop-2 + RK4 epilogue ----
            for (int w = gw; w < NN / 4; w += nwarps) {
                int row = w * 4 + qq;
                Acc8 g = row_gather_quarter(g_t1h, g_ecol2, g_rp2, row, m);
                float sr = g_dinv_r[row];
                float v0 = -sr * g.a0, v1 = -sr * g.a1, v2 = -sr * g.a2, v3 = -sr * g.a3;
                float v4 = -sr * g.a4, v5 = -sr * g.a5, v6 = -sr * g.a6, v7 = -sr * g.a7;

                int o4 = row * 8 + m;
                float p = g_premul[row];
                float u0, u1, u2, u3, u4, u5, u6, u7;

                if (sub == 1) {
                    g_acch[o4] = pack8h(v0, v1, v2, v3, v4, v5, v6, v7);
                    uint4 rh4 = ((const uint4*)g_rh)[o4];
                    float2 fa = __half22float2(*(const __half2*)&rh4.x);
                    float2 fb = __half22float2(*(const __half2*)&rh4.y);
                    float2 fc = __half22float2(*(const __half2*)&rh4.z);
                    float2 fd = __half22float2(*(const __half2*)&rh4.w);
                    u0 = fa.x + HALF_DT * v0; u1 = fa.y + HALF_DT * v1;
                    u2 = fb.x + HALF_DT * v2; u3 = fb.y + HALF_DT * v3;
                    u4 = fc.x + HALF_DT * v4; u5 = fc.y + HALF_DT * v5;
                    u6 = fd.x + HALF_DT * v6; u7 = fd.y + HALF_DT * v7;
                } else if (sub < 4) {
                    uint4 a4 = g_acch[o4];
                    float2 aa = __half22float2(*(const __half2*)&a4.x);
                    float2 ab = __half22float2(*(const __half2*)&a4.y);
                    float2 ac = __half22float2(*(const __half2*)&a4.z);
                    float2 ad = __half22float2(*(const __half2*)&a4.w);
                    g_acch[o4] = pack8h(aa.x + 2.f * v0, aa.y + 2.f * v1,
                                        ab.x + 2.f * v2, ab.y + 2.f * v3,
                                        ac.x + 2.f * v4, ac.y + 2.f * v5,
                                        ad.x + 2.f * v6, ad.y + 2.f * v7);
                    uint4 rh4 = ((const uint4*)g_rh)[o4];
                    float2 fa = __half22float2(*(const __half2*)&rh4.x);
                    float2 fb = __half22float2(*(const __half2*)&rh4.y);
                    float2 fc = __half22float2(*(const __half2*)&rh4.z);
                    float2 fd = __half22float2(*(const __half2*)&rh4.w);
                    float cdt = (sub == 2) ? HALF_DT : DTC;
                    u0 = fa.x + cdt * v0; u1 = fa.y + cdt * v1;
                    u2 = fb.x + cdt * v2; u3 = fb.y + cdt * v3;
                    u4 = fc.x + cdt * v4; u5 = fc.y + cdt * v5;
                    u6 = fd.x + cdt * v6; u7 = fd.y + cdt * v7;
                } else {
                    uint4 a4 = g_acch[o4];
                    float2 aa = __half22float2(*(const __half2*)&a4.x);
                    float2 ab = __half22float2(*(const __half2*)&a4.y);
                    float2 ac = __half22float2(*(const __half2*)&a4.z);
                    float2 ad = __half22float2(*(const __half2*)&a4.w);
                    int oA = row * 16 + 2 * m;
                    float4 ra = ((const float4*)rin)[oA];
                    float4 rb = ((const float4*)rin)[oA + 1];
                    u0 = ra.x + DT6 * (aa.x + v0); u1 = ra.y + DT6 * (aa.y + v1);
                    u2 = ra.z + DT6 * (ab.x + v2); u3 = ra.w + DT6 * (ab.y + v3);
                    u4 = rb.x + DT6 * (ac.x + v4); u5 = rb.y + DT6 * (ac.y + v5);
                    u6 = rb.z + DT6 * (ad.x + v6); u7 = rb.w + DT6 * (ad.y + v7);
                    ((float4*)rnext)[oA]     = make_float4(u0, u1, u2, u3);
                    ((float4*)rnext)[oA + 1] = make_float4(u4, u5, u6, u7);
                    ((uint4*)g_rh)[o4] = pack8h(u0, u1, u2, u3, u4, u5, u6, u7);
                }
                ((uint4*)g_uh)[o4] = pack8h(p * u0, p * u1, p * u2, p * u3,
                                            p * u4, p * u5, p * u6, p * u7);
            }
            if (!(step == 4 && sub == 4)) grid_barrier(++bar);
        }
    }
}

// ---------------- launch ----------------
extern "C" void kernel_launch(void* const* d_in, const int* in_sizes, int n_in,
                              void* d_out, int out_size) {
    const float* r0   = (const float*)d_in[0];
    const int*   eidx = (const int*)d_in[1];
    const int*   mask = (const int*)d_in[2];
    const int* row = eidx;
    const int* col = eidx + NE;
    float* out = (float*)d_out;

    // CSR + normalization build
    zero_kernel<<<(NN + 255) / 256, 256>>>();
    hist_kernel<<<(NE + 255) / 256, 256>>>(row, col, mask);
    dinv_kernel<<<(NN + 255) / 256, 256>>>(mask);
    scan_block_fused<<<2 * NB, 1024>>>();
    scan_part_fused <<<1, 64>>>();
    scan_add_fused  <<<2 * NB, 1024>>>();
    scatter_kernel  <<<(NE + 255) / 256, 256>>>(row, col, mask);

    // persistent RK4 mainloop: one block per SM, all co-resident
    int dev = 0, sm = 148;
    cudaGetDevice(&dev);
    cudaDeviceGetAttribute(&sm, cudaDevAttrMultiProcessorCount, dev);
    rk4_persistent<<<sm, 1024>>>(r0, out);
}